// round 11
// baseline (speedup 1.0000x reference)
#include <cuda_runtime.h>
#include <stdint.h>

#define D 8
#define MAX_WORDS 32768            // (1024*1024)/32 cells -> 128 KB bitmap

// 1 bit per (src,dst) cell. Statically zero; fill_kernel self-clears each
// word after consuming it, so every replay sees a clean bitmap.
__device__ unsigned g_bitmap[MAX_WORDS];

__global__ void set_bitmap(const int* __restrict__ ei, int e, int n) {
    int i = blockIdx.x * blockDim.x + threadIdx.x;
    if (i >= e) return;
    unsigned cell = (unsigned)ei[i] * (unsigned)n + (unsigned)ei[e + i];
    atomicOr(&g_bitmap[cell >> 5], 1u << (cell & 31));
}

// One block owns 128 cells (4 bitmap words = 32 KB of output).
// Phase 1: pure unrolled store stream (8 STG.128/thread, no loads).
// Phase 2: rare edge overwrite. Thread t zero-stores float4 slot (16k+g, q)
// and overwrites (16j+g, q) — identical slots, same thread, program order:
// no inter-thread hazard, no barrier needed between phases.
__global__ void __launch_bounds__(256) fill_kernel(
        const float* __restrict__ x,
        const float* __restrict__ W,
        float4* __restrict__ out4,
        int n) {
    int t = threadIdx.x;
    unsigned blockCell = blockIdx.x * 128u;
    __shared__ unsigned sw[4];

    if (t < 4) {
        unsigned wordIdx = (blockCell >> 5) + t;
        sw[t] = g_bitmap[wordIdx];
        g_bitmap[wordIdx] = 0;               // consume: clean for next replay
    }

    // Phase 1: pure store stream (bitmap LDG latency hidden behind it).
    float4* base = out4 + (size_t)blockCell * 16;
    const float4 z = make_float4(0.f, 0.f, 0.f, 0.f);
    #pragma unroll
    for (int k = 0; k < 8; k++) base[k * 256 + t] = z;

    __syncthreads();                          // publish sw

    // Phase 2: overwrite edge cells (~3% of cells).
    int g = t >> 4;                           // cell sub-index within stride
    int q = t & 15;                           // float4 slot within cell
    #pragma unroll
    for (int j = 0; j < 8; j++) {
        unsigned c = (unsigned)(j * 16 + g);  // 0..127
        if ((sw[c >> 5] >> (c & 31)) & 1u) {
            unsigned cell = blockCell + c;
            unsigned src, dst;
            if (n == 1024) { src = cell >> 10; dst = cell & 1023u; }
            else           { src = cell / (unsigned)n; dst = cell - src * (unsigned)n; }

            const float4* xs = (const float4*)(x + src * D);
            const float4* xd = (const float4*)(x + dst * D);
            float4 a0 = __ldg(xs), a1 = __ldg(xs + 1);
            float4 b0 = __ldg(xd), b1 = __ldg(xd + 1);

            float dv[D];
            dv[0] = fabsf(a0.x - b0.x); dv[1] = fabsf(a0.y - b0.y);
            dv[2] = fabsf(a0.z - b0.z); dv[3] = fabsf(a0.w - b0.w);
            dv[4] = fabsf(a1.x - b1.x); dv[5] = fabsf(a1.y - b1.y);
            dv[6] = fabsf(a1.z - b1.z); dv[7] = fabsf(a1.w - b1.w);

            float acc[4];
            #pragma unroll
            for (int r = 0; r < 4; r++) {
                const float4* wp = (const float4*)(W + (q * 4 + r) * D);
                float4 w0 = __ldg(wp), w1 = __ldg(wp + 1);
                acc[r] = w0.x * dv[0] + w0.y * dv[1] + w0.z * dv[2] + w0.w * dv[3]
                       + w1.x * dv[4] + w1.y * dv[5] + w1.z * dv[6] + w1.w * dv[7];
            }
            out4[(size_t)cell * 16 + q] = make_float4(acc[0], acc[1], acc[2], acc[3]);
        }
    }
}

extern "C" void kernel_launch(void* const* d_in, const int* in_sizes, int n_in,
                              void* d_out, int out_size) {
    const float* x  = (const float*)d_in[0];
    const int*   ei = (const int*)d_in[1];    // int64 in reference, int32 here
    const float* W  = (const float*)d_in[2];

    int n = in_sizes[0] / D;     // 1024
    int e = in_sizes[1] / 2;     // 32768

    set_bitmap<<<(e + 255) / 256, 256>>>(ei, e, n);

    int nblocks = (n * n) / 128;              // 8192 for n=1024
    fill_kernel<<<nblocks, 256>>>(x, W, (float4*)d_out, n);
}